// round 1
// baseline (speedup 1.0000x reference)
#include <cuda_runtime.h>
#include <cstdint>
#include <cstddef>

#define BB 4
#define PP 256
#define FIN 512
#define FOUT 512
#define NROWS (BB*PP)   // 1024

// ---------------- scratch (device globals: no allocations allowed) ----------
__device__ float g_H[NROWS * FOUT];                 // fc output h (2 MB)
__device__ float g_S[BB * PP * PP];                 // Gram matrix h·h^T (1 MB)
__device__ unsigned long long g_h1[NROWS];
__device__ unsigned long long g_h2[NROWS];
__device__ double g_loss;

// ---------------- hash + zero-init kernel -----------------------------------
__device__ __forceinline__ unsigned long long mix64(unsigned long long x) {
    x ^= x >> 30; x *= 0xbf58476d1ce4e5b9ULL;
    x ^= x >> 27; x *= 0x94d049bb133111ebULL;
    x ^= x >> 31;
    return x;
}

// grid 128 x 256 threads = 1024 warps = 1 warp per label row.
// Also zeroes g_S (needed by split-K atomic epilogue) and g_loss.
__global__ void hash_zero_kernel(const float* __restrict__ labels) {
    int gt = blockIdx.x * blockDim.x + threadIdx.x;
    if (gt == 0) g_loss = 0.0;
    // zero the Gram buffer (262144 floats / 32768 threads = 8 each)
    for (int i = gt; i < BB * PP * PP; i += gridDim.x * blockDim.x) g_S[i] = 0.0f;

    int warp = gt >> 5;
    int lane = threadIdx.x & 31;
    const float* row = labels + (size_t)warp * FIN;
    unsigned long long h1 = 0ull, h2 = 0ull;
#pragma unroll
    for (int i = 0; i < FIN / 32; i++) {
        int f = lane + 32 * i;
        float v = row[f];
        unsigned int bits = __float_as_uint(v);
        if (v == 0.0f) bits = 0u;           // canonicalize -0 == +0
        unsigned long long x =
            ((unsigned long long)bits) ^ ((unsigned long long)(f + 1) * 0x9E3779B97F4A7C15ULL);
        h1 += mix64(x);
        h2 += mix64(x ^ 0xA5A5A5A5DEADBEEFULL);
    }
#pragma unroll
    for (int o = 16; o > 0; o >>= 1) {
        h1 += __shfl_down_sync(0xffffffffu, h1, o);
        h2 += __shfl_down_sync(0xffffffffu, h2, o);
    }
    if (lane == 0) { g_h1[warp] = h1; g_h2[warp] = h2; }
}

// ---------------- GEMM1: H = inputs(1024x512) * W(512x512)^T + b ------------
// 64x64 tile, BK=16, 4x4 microtile, 256 threads. grid (N/64=8, M/64=16).
__global__ void gemm1_kernel(const float* __restrict__ A,
                             const float* __restrict__ Bm,
                             const float* __restrict__ bias) {
    constexpr int BK = 16;
    __shared__ float As[BK][64 + 4];
    __shared__ float Bs[BK][64 + 4];

    const int m0 = blockIdx.y * 64;
    const int n0 = blockIdx.x * 64;
    const int tid = threadIdx.x;
    const int tx = tid & 15;   // n direction
    const int ty = tid >> 4;   // m direction

    float acc[4][4];
#pragma unroll
    for (int i = 0; i < 4; i++)
#pragma unroll
        for (int j = 0; j < 4; j++) acc[i][j] = 0.0f;

    for (int k0 = 0; k0 < FIN; k0 += BK) {
#pragma unroll
        for (int idx = tid; idx < 64 * BK; idx += 256) {
            int r = idx / BK, c = idx % BK;
            As[c][r] = A[(size_t)(m0 + r) * FIN + k0 + c];
        }
#pragma unroll
        for (int idx = tid; idx < 64 * BK; idx += 256) {
            int r = idx / BK, c = idx % BK;
            Bs[c][r] = Bm[(size_t)(n0 + r) * FIN + k0 + c];
        }
        __syncthreads();
#pragma unroll
        for (int kk = 0; kk < BK; kk++) {
            float4 av = *reinterpret_cast<const float4*>(&As[kk][ty * 4]);
            float4 bv = *reinterpret_cast<const float4*>(&Bs[kk][tx * 4]);
            float a[4] = {av.x, av.y, av.z, av.w};
            float bb[4] = {bv.x, bv.y, bv.z, bv.w};
#pragma unroll
            for (int i = 0; i < 4; i++)
#pragma unroll
                for (int j = 0; j < 4; j++) acc[i][j] = fmaf(a[i], bb[j], acc[i][j]);
        }
        __syncthreads();
    }
#pragma unroll
    for (int i = 0; i < 4; i++) {
        int m = m0 + ty * 4 + i;
#pragma unroll
        for (int j = 0; j < 4; j++) {
            int n = n0 + tx * 4 + j;
            g_H[(size_t)m * FOUT + n] = acc[i][j] + bias[n];
        }
    }
}

// ---------------- GEMM2: S_b = H_b * H_b^T, split-K x2, atomic epilogue -----
// grid (4, 4, 8): z = batch*2 + ksplit. 64x64 tile, 4x4 microtile.
__global__ void gemm2_kernel() {
    constexpr int BK = 16;
    __shared__ float As[BK][64 + 4];
    __shared__ float Bs[BK][64 + 4];

    const int b  = blockIdx.z >> 1;
    const int kz = blockIdx.z & 1;
    const int m0 = blockIdx.y * 64;
    const int n0 = blockIdx.x * 64;
    const int tid = threadIdx.x;
    const int tx = tid & 15;
    const int ty = tid >> 4;

    const float* Ab = g_H + (size_t)b * PP * FOUT;
    float* Cb = g_S + (size_t)b * PP * PP;
    const int kbeg = kz * (FOUT / 2);
    const int kend = kbeg + (FOUT / 2);

    float acc[4][4];
#pragma unroll
    for (int i = 0; i < 4; i++)
#pragma unroll
        for (int j = 0; j < 4; j++) acc[i][j] = 0.0f;

    for (int k0 = kbeg; k0 < kend; k0 += BK) {
#pragma unroll
        for (int idx = tid; idx < 64 * BK; idx += 256) {
            int r = idx / BK, c = idx % BK;
            As[c][r] = Ab[(size_t)(m0 + r) * FOUT + k0 + c];
        }
#pragma unroll
        for (int idx = tid; idx < 64 * BK; idx += 256) {
            int r = idx / BK, c = idx % BK;
            Bs[c][r] = Ab[(size_t)(n0 + r) * FOUT + k0 + c];
        }
        __syncthreads();
#pragma unroll
        for (int kk = 0; kk < BK; kk++) {
            float4 av = *reinterpret_cast<const float4*>(&As[kk][ty * 4]);
            float4 bv = *reinterpret_cast<const float4*>(&Bs[kk][tx * 4]);
            float a[4] = {av.x, av.y, av.z, av.w};
            float bb[4] = {bv.x, bv.y, bv.z, bv.w};
#pragma unroll
            for (int i = 0; i < 4; i++)
#pragma unroll
                for (int j = 0; j < 4; j++) acc[i][j] = fmaf(a[i], bb[j], acc[i][j]);
        }
        __syncthreads();
    }
#pragma unroll
    for (int i = 0; i < 4; i++) {
        int m = m0 + ty * 4 + i;
#pragma unroll
        for (int j = 0; j < 4; j++) {
            int n = n0 + tx * 4 + j;
            atomicAdd(&Cb[(size_t)m * PP + n], acc[i][j]);
        }
    }
}

// ---------------- softmax + KL ----------------------------------------------
// grid (B, 8), 256 threads: 8 warps x 4 rows = 32 rows per block.
// scores[p][q] = S[p][q] * inv[p] * inv[q] / TAU, inv from Gram diagonal.
__global__ void softmax_kl_kernel() {
    const int b = blockIdx.x;
    const int rowBase = blockIdx.y * 32;
    __shared__ float inv[PP];
    __shared__ unsigned long long sh1[PP];
    __shared__ unsigned long long sh2[PP];

    const int tid = threadIdx.x;
    {
        int q = tid;
        float d = g_S[((size_t)b * PP + q) * PP + q];   // = ||h_q||^2
        inv[q] = 1.0f / fmaxf(sqrtf(d), 1e-12f);
        sh1[q] = g_h1[b * PP + q];
        sh2[q] = g_h2[b * PP + q];
    }
    __syncthreads();

    const int w = tid >> 5, lane = tid & 31;
    const float INV_TAU = 1.0f / 0.07f;
    double local = 0.0;

    for (int r = 0; r < 4; r++) {
        int p = rowBase + w * 4 + r;
        const float* Sr = g_S + ((size_t)b * PP + p) * PP;
        float ip = inv[p];
        float s[8];
        float mx = -1e30f;
#pragma unroll
        for (int j = 0; j < 8; j++) {
            int q = lane + 32 * j;
            s[j] = Sr[q] * ip * inv[q] * INV_TAU;
            mx = fmaxf(mx, s[j]);
        }
#pragma unroll
        for (int o = 16; o > 0; o >>= 1) mx = fmaxf(mx, __shfl_xor_sync(0xffffffffu, mx, o));
        float z = 0.0f;
#pragma unroll
        for (int j = 0; j < 8; j++) z += __expf(s[j] - mx);
#pragma unroll
        for (int o = 16; o > 0; o >>= 1) z += __shfl_xor_sync(0xffffffffu, z, o);
        float lse = mx + logf(z);

        unsigned long long h1p = sh1[p], h2p = sh2[p];
        int cnt = 0;
        bool match[8];
#pragma unroll
        for (int j = 0; j < 8; j++) {
            int q = lane + 32 * j;
            match[j] = (sh1[q] == h1p) && (sh2[q] == h2p);
            cnt += match[j] ? 1 : 0;
        }
#pragma unroll
        for (int o = 16; o > 0; o >>= 1) cnt += __shfl_xor_sync(0xffffffffu, cnt, o);

        float logn = logf((float)cnt);
        float contrib = 0.0f;
#pragma unroll
        for (int j = 0; j < 8; j++) {
            if (match[j]) {
                float lp = s[j] - lse;                               // log softmax
                lp = fminf(fmaxf(lp, -11.512925464970229f),          // log(1e-5)
                           -1.0000050000290891e-05f);                // log(1-1e-5)
                contrib += (-logn - lp);
            }
        }
#pragma unroll
        for (int o = 16; o > 0; o >>= 1) contrib += __shfl_xor_sync(0xffffffffu, contrib, o);
        if (lane == 0) local += (double)contrib / (double)cnt;
    }
    if (lane == 0 && local != 0.0) atomicAdd(&g_loss, local);
}

__global__ void finalize_kernel(float* __restrict__ out) {
    if (threadIdx.x == 0) out[0] = (float)(g_loss * (1.0 / (double)(BB * PP)));
}

// ---------------- launch -----------------------------------------------------
extern "C" void kernel_launch(void* const* d_in, const int* in_sizes, int n_in,
                              void* d_out, int out_size) {
    const float* inputs = (const float*)d_in[0];
    const float* labels = (const float*)d_in[1];
    const float* W      = (const float*)d_in[2];
    const float* bias   = (const float*)d_in[3];
    float* out = (float*)d_out;

    hash_zero_kernel<<<128, 256>>>(labels);
    gemm1_kernel<<<dim3(FOUT / 64, NROWS / 64), 256>>>(inputs, W, bias);
    gemm2_kernel<<<dim3(PP / 64, PP / 64, BB * 2), 256>>>();
    softmax_kl_kernel<<<dim3(BB, PP / 32), 256>>>();
    finalize_kernel<<<1, 32>>>(out);
}

// round 2
// speedup vs baseline: 2.1287x; 2.1287x over previous
#include <cuda_runtime.h>
#include <cstdint>
#include <cstddef>

#define BB 4
#define PP 256
#define FIN 512
#define FOUT 512
#define NROWS (BB*PP)   // 1024

// ---------------- device scratch (no allocations allowed) -------------------
__device__ float g_H[NROWS * FOUT];          // fc output h (+bias), 2 MB
__device__ float g_S0[BB * PP * PP];         // Gram partial (k 0..255), 1 MB
__device__ float g_S1[BB * PP * PP];         // Gram partial (k 256..511), 1 MB
__device__ unsigned long long g_h1[NROWS];
__device__ unsigned long long g_h2[NROWS];
__device__ double g_loss;

// ---------------- label-row hashing ------------------------------------------
__device__ __forceinline__ unsigned long long mix64(unsigned long long x) {
    x ^= x >> 30; x *= 0xbf58476d1ce4e5b9ULL;
    x ^= x >> 27; x *= 0x94d049bb133111ebULL;
    x ^= x >> 31;
    return x;
}

// 128 blocks x 256 threads = 1024 warps = one warp per label row.
__global__ void hash_kernel(const float* __restrict__ labels) {
    int gt = blockIdx.x * blockDim.x + threadIdx.x;
    if (gt == 0) g_loss = 0.0;
    int warp = gt >> 5;
    int lane = threadIdx.x & 31;
    const float4* row = reinterpret_cast<const float4*>(labels + (size_t)warp * FIN);
    unsigned long long h1 = 0ull, h2 = 0ull;
#pragma unroll
    for (int i = 0; i < 4; i++) {
        float4 v = row[lane + 32 * i];
        int fb = (lane + 32 * i) * 4;
        float vv[4] = {v.x, v.y, v.z, v.w};
#pragma unroll
        for (int j = 0; j < 4; j++) {
            unsigned int bits = __float_as_uint(vv[j]);
            if (vv[j] == 0.0f) bits = 0u;     // canonicalize -0 == +0
            unsigned long long x = (unsigned long long)bits
                ^ ((unsigned long long)(fb + j + 1) * 0x9E3779B97F4A7C15ULL);
            h1 += mix64(x);
            h2 += mix64(x ^ 0xA5A5A5A5DEADBEEFULL);
        }
    }
#pragma unroll
    for (int o = 16; o > 0; o >>= 1) {
        h1 += __shfl_down_sync(0xffffffffu, h1, o);
        h2 += __shfl_down_sync(0xffffffffu, h2, o);
    }
    if (lane == 0) { g_h1[warp] = h1; g_h2[warp] = h2; }
}

// ---------------- FMA-bound 64x64 GEMM core ----------------------------------
// 128 threads, 8x4 microtile (tx = tid&15 -> 4 n-cols, ty = tid>>4 -> 8 m-rows).
// BK=32, double-buffered smem, scalar LDS conflict-free via stride-33 pad.
// C[m][n] = sum_k A0[m][k] * B0[n][k]   (both operands K-major, ld = row stride)
template<int NS>
__device__ __forceinline__ void gemm_core(const float* __restrict__ A0,
                                          const float* __restrict__ B0,
                                          int ld, float acc[8][4]) {
    __shared__ float As[2][64][33];
    __shared__ float Bs[2][64][33];
    const int tid = threadIdx.x;
    const int r0 = tid >> 3;        // 0..15 (row within tile, +16q)
    const int kc = tid & 7;         // float4 column within 32-k slice
    const int tx = tid & 15;
    const int ty = tid >> 4;

    const float* Arow = A0 + (size_t)r0 * ld + kc * 4;
    const float* Brow = B0 + (size_t)r0 * ld + kc * 4;

    float4 pa[4], pb[4];

    auto LDG = [&](int s) {
#pragma unroll
        for (int q = 0; q < 4; q++) {
            pa[q] = *reinterpret_cast<const float4*>(Arow + (size_t)(16 * q) * ld + s * 32);
            pb[q] = *reinterpret_cast<const float4*>(Brow + (size_t)(16 * q) * ld + s * 32);
        }
    };
    auto STS = [&](int buf) {
#pragma unroll
        for (int q = 0; q < 4; q++) {
            int r = r0 + 16 * q;
            As[buf][r][kc * 4 + 0] = pa[q].x;
            As[buf][r][kc * 4 + 1] = pa[q].y;
            As[buf][r][kc * 4 + 2] = pa[q].z;
            As[buf][r][kc * 4 + 3] = pa[q].w;
            Bs[buf][r][kc * 4 + 0] = pb[q].x;
            Bs[buf][r][kc * 4 + 1] = pb[q].y;
            Bs[buf][r][kc * 4 + 2] = pb[q].z;
            Bs[buf][r][kc * 4 + 3] = pb[q].w;
        }
    };

    LDG(0);
    STS(0);
    __syncthreads();

#pragma unroll 1
    for (int s = 0; s < NS; s++) {
        const int buf = s & 1;
        if (s + 1 < NS) LDG(s + 1);
#pragma unroll
        for (int kk = 0; kk < 32; kk++) {
            float a[8], b[4];
#pragma unroll
            for (int i = 0; i < 8; i++) a[i] = As[buf][ty * 8 + i][kk];
#pragma unroll
            for (int j = 0; j < 4; j++) b[j] = Bs[buf][tx * 4 + j][kk];
#pragma unroll
            for (int i = 0; i < 8; i++)
#pragma unroll
                for (int j = 0; j < 4; j++) acc[i][j] = fmaf(a[i], b[j], acc[i][j]);
        }
        if (s + 1 < NS) STS(buf ^ 1);
        __syncthreads();
    }
}

// ---------------- GEMM1: g_H = inputs(1024x512) @ W(512x512)^T + bias --------
// grid (FOUT/64=8, NROWS/64=16) = 128 blocks x 128 threads, no split-K.
__global__ __launch_bounds__(128, 1)
void gemm1_kernel(const float* __restrict__ A, const float* __restrict__ W,
                  const float* __restrict__ bias) {
    const int m0 = blockIdx.y * 64;
    const int n0 = blockIdx.x * 64;
    float acc[8][4];
#pragma unroll
    for (int i = 0; i < 8; i++)
#pragma unroll
        for (int j = 0; j < 4; j++) acc[i][j] = 0.0f;

    gemm_core<16>(A + (size_t)m0 * FIN, W + (size_t)n0 * FIN, FIN, acc);

    const int tx = threadIdx.x & 15, ty = threadIdx.x >> 4;
    float4 bb = *reinterpret_cast<const float4*>(bias + n0 + tx * 4);
#pragma unroll
    for (int i = 0; i < 8; i++) {
        float4 o = make_float4(acc[i][0] + bb.x, acc[i][1] + bb.y,
                               acc[i][2] + bb.z, acc[i][3] + bb.w);
        *reinterpret_cast<float4*>(g_H + (size_t)(m0 + ty * 8 + i) * FOUT + n0 + tx * 4) = o;
    }
}

// ---------------- GEMM2: Gram S_b = H_b @ H_b^T, split-K 2 partial buffers ---
// grid (4, 4, 8): z = b*2 + kz. 128 blocks x 128 threads, plain stores.
__global__ __launch_bounds__(128, 1)
void gemm2_kernel() {
    const int b  = blockIdx.z >> 1;
    const int kz = blockIdx.z & 1;
    const int m0 = blockIdx.y * 64;
    const int n0 = blockIdx.x * 64;
    const float* Hb = g_H + (size_t)b * PP * FOUT + kz * 256;

    float acc[8][4];
#pragma unroll
    for (int i = 0; i < 8; i++)
#pragma unroll
        for (int j = 0; j < 4; j++) acc[i][j] = 0.0f;

    gemm_core<8>(Hb + (size_t)m0 * FOUT, Hb + (size_t)n0 * FOUT, FOUT, acc);

    float* C = (kz ? g_S1 : g_S0) + (size_t)b * PP * PP;
    const int tx = threadIdx.x & 15, ty = threadIdx.x >> 4;
#pragma unroll
    for (int i = 0; i < 8; i++) {
        float4 o = make_float4(acc[i][0], acc[i][1], acc[i][2], acc[i][3]);
        *reinterpret_cast<float4*>(C + (size_t)(m0 + ty * 8 + i) * PP + n0 + tx * 4) = o;
    }
}

// ---------------- softmax + KL -----------------------------------------------
// grid (B=4, 32) = 128 blocks x 128 threads: 4 warps x 2 rows = 8 rows/block.
__global__ void softmax_kl_kernel() {
    const int b = blockIdx.x;
    const int rowBase = blockIdx.y * 8;
    __shared__ float inv[PP];
    __shared__ unsigned long long sh1[PP];
    __shared__ unsigned long long sh2[PP];
    __shared__ double wsum[4];

    const int tid = threadIdx.x;
#pragma unroll
    for (int t = tid; t < PP; t += 128) {
        size_t di = ((size_t)b * PP + t) * PP + t;
        float d = g_S0[di] + g_S1[di];          // ||h_t||^2 from Gram diagonal
        inv[t] = 1.0f / fmaxf(sqrtf(d), 1e-12f);
        sh1[t] = g_h1[b * PP + t];
        sh2[t] = g_h2[b * PP + t];
    }
    __syncthreads();

    const int w = tid >> 5, lane = tid & 31;
    const float INV_TAU = 1.0f / 0.07f;
    double local = 0.0;

#pragma unroll
    for (int r = 0; r < 2; r++) {
        int p = rowBase + w * 2 + r;
        const float* S0r = g_S0 + ((size_t)b * PP + p) * PP;
        const float* S1r = g_S1 + ((size_t)b * PP + p) * PP;
        float ip = inv[p] * INV_TAU;
        float s[8];
        float mx = -1e30f;
#pragma unroll
        for (int j = 0; j < 8; j++) {
            int q = lane + 32 * j;
            s[j] = (S0r[q] + S1r[q]) * ip * inv[q];
            mx = fmaxf(mx, s[j]);
        }
#pragma unroll
        for (int o = 16; o > 0; o >>= 1) mx = fmaxf(mx, __shfl_xor_sync(0xffffffffu, mx, o));
        float z = 0.0f;
#pragma unroll
        for (int j = 0; j < 8; j++) z += __expf(s[j] - mx);
#pragma unroll
        for (int o = 16; o > 0; o >>= 1) z += __shfl_xor_sync(0xffffffffu, z, o);
        float lse = mx + logf(z);

        unsigned long long h1p = sh1[p], h2p = sh2[p];
        int cnt = 0;
        bool match[8];
#pragma unroll
        for (int j = 0; j < 8; j++) {
            int q = lane + 32 * j;
            match[j] = (sh1[q] == h1p) && (sh2[q] == h2p);
            cnt += match[j] ? 1 : 0;
        }
#pragma unroll
        for (int o = 16; o > 0; o >>= 1) cnt += __shfl_xor_sync(0xffffffffu, cnt, o);

        float logn = logf((float)cnt);
        float contrib = 0.0f;
#pragma unroll
        for (int j = 0; j < 8; j++) {
            if (match[j]) {
                float lp = s[j] - lse;                               // log softmax
                lp = fminf(fmaxf(lp, -11.512925464970229f),          // log(1e-5)
                           -1.0000050000290891e-05f);                // log(1-1e-5)
                contrib += (-logn - lp);
            }
        }
#pragma unroll
        for (int o = 16; o > 0; o >>= 1) contrib += __shfl_xor_sync(0xffffffffu, contrib, o);
        if (lane == 0) local += (double)contrib / (double)cnt;
    }

    if (lane == 0) wsum[w] = local;
    __syncthreads();
    if (tid == 0) {
        double blk = wsum[0] + wsum[1] + wsum[2] + wsum[3];
        atomicAdd(&g_loss, blk);
    }
}

__global__ void finalize_kernel(float* __restrict__ out) {
    if (threadIdx.x == 0) out[0] = (float)(g_loss * (1.0 / (double)(BB * PP)));
}

// ---------------- launch -----------------------------------------------------
extern "C" void kernel_launch(void* const* d_in, const int* in_sizes, int n_in,
                              void* d_out, int out_size) {
    const float* inputs = (const float*)d_in[0];
    const float* labels = (const float*)d_in[1];
    const float* W      = (const float*)d_in[2];
    const float* bias   = (const float*)d_in[3];
    float* out = (float*)d_out;

    hash_kernel<<<128, 256>>>(labels);
    gemm1_kernel<<<dim3(FOUT / 64, NROWS / 64), 128>>>(inputs, W, bias);
    gemm2_kernel<<<dim3(PP / 64, PP / 64, BB * 2), 128>>>();
    softmax_kl_kernel<<<dim3(BB, PP / 8), 128>>>();
    finalize_kernel<<<1, 32>>>(out);
}

// round 4
// speedup vs baseline: 2.3366x; 1.0977x over previous
#include <cuda_runtime.h>
#include <mma.h>
#include <cstdint>
#include <cstddef>

using namespace nvcuda;

#define BB 4
#define PP 256
#define FIN 512
#define FOUT 512
#define NROWS (BB*PP)   // 1024

// ---------------- device scratch (no allocations allowed) -------------------
__device__ float g_H[NROWS * FOUT];          // fc output h (+bias), 2 MB
__device__ float g_S0[BB * PP * PP];         // Gram partial (k 0..255)
__device__ float g_S1[BB * PP * PP];         // Gram partial (k 256..511)
__device__ unsigned long long g_h1[NROWS];
__device__ unsigned long long g_h2[NROWS];
__device__ double g_loss;

// ================= WMMA TF32 GEMM core ======================================
// C[64 x 64] = A[64 x K] * B[64 x K]^T, K = NS*32. 128 threads = 4 warps (2x2),
// each warp a 32x32 output via 2x2 of m16n16k8 tf32 fragments.
// Double-buffered smem, BK=32, register-staged global prefetch.
template<int NS, bool BIAS>
__device__ __forceinline__ void wmma_core(const float* __restrict__ A0,
                                          const float* __restrict__ B0,
                                          const float* __restrict__ biasTile,
                                          float* __restrict__ Ctile, int ldc, int ld) {
    __shared__ float As[2][64][36];
    __shared__ float Bs[2][64][36];

    const int tid = threadIdx.x;
    const int wid = tid >> 5;
    const int wm = wid >> 1;          // warp row (0..1) -> rows wm*32
    const int wn = wid & 1;           // warp col (0..1) -> cols wn*32
    const int r0 = tid >> 3;          // 0..15
    const int kc = tid & 7;           // float4 slot in 32-wide k slice

    const float* Arow = A0 + (size_t)r0 * ld + kc * 4;
    const float* Brow = B0 + (size_t)r0 * ld + kc * 4;

    float4 pa[4], pb[4];
    auto LDG = [&](int s) {
#pragma unroll
        for (int q = 0; q < 4; q++) {
            pa[q] = *reinterpret_cast<const float4*>(Arow + (size_t)(16 * q) * ld + s * 32);
            pb[q] = *reinterpret_cast<const float4*>(Brow + (size_t)(16 * q) * ld + s * 32);
        }
    };
    auto STS = [&](int buf) {
#pragma unroll
        for (int q = 0; q < 4; q++) {
            int r = r0 + 16 * q;
            *reinterpret_cast<float4*>(&As[buf][r][kc * 4]) = pa[q];
            *reinterpret_cast<float4*>(&Bs[buf][r][kc * 4]) = pb[q];
        }
    };

    wmma::fragment<wmma::accumulator, 16, 16, 8, float> c[2][2];
#pragma unroll
    for (int i = 0; i < 2; i++)
#pragma unroll
        for (int j = 0; j < 2; j++) wmma::fill_fragment(c[i][j], 0.0f);

    LDG(0);
    STS(0);
    __syncthreads();

#pragma unroll 1
    for (int s = 0; s < NS; s++) {
        const int buf = s & 1;
        if (s + 1 < NS) LDG(s + 1);
#pragma unroll
        for (int ks = 0; ks < 4; ks++) {
            wmma::fragment<wmma::matrix_a, 16, 16, 8, wmma::precision::tf32, wmma::row_major> a[2];
            wmma::fragment<wmma::matrix_b, 16, 16, 8, wmma::precision::tf32, wmma::col_major> bfr[2];
#pragma unroll
            for (int i = 0; i < 2; i++) {
                wmma::load_matrix_sync(a[i], &As[buf][wm * 32 + i * 16][ks * 8], 36);
#pragma unroll
                for (int t = 0; t < a[i].num_elements; t++)
                    a[i].x[t] = wmma::__float_to_tf32(a[i].x[t]);
            }
#pragma unroll
            for (int j = 0; j < 2; j++) {
                wmma::load_matrix_sync(bfr[j], &Bs[buf][wn * 32 + j * 16][ks * 8], 36);
#pragma unroll
                for (int t = 0; t < bfr[j].num_elements; t++)
                    bfr[j].x[t] = wmma::__float_to_tf32(bfr[j].x[t]);
            }
#pragma unroll
            for (int i = 0; i < 2; i++)
#pragma unroll
                for (int j = 0; j < 2; j++) wmma::mma_sync(c[i][j], a[i], bfr[j], c[i][j]);
        }
        if (s + 1 < NS) STS(buf ^ 1);
        __syncthreads();
    }

    if (BIAS) {
        // stage through smem to add per-column bias, then vectorized STG
        float* stage = &As[0][0][0];             // 64*68 floats = 17408 B < 36864 B
#pragma unroll
        for (int i = 0; i < 2; i++)
#pragma unroll
            for (int j = 0; j < 2; j++)
                wmma::store_matrix_sync(stage + (size_t)(wm * 32 + i * 16) * 68 + wn * 32 + j * 16,
                                        c[i][j], 68, wmma::mem_row_major);
        __syncthreads();
#pragma unroll
        for (int t = 0; t < 8; t++) {
            int f4 = tid + t * 128;              // 0..1023 float4 ids
            int row = f4 >> 4, c4 = (f4 & 15) * 4;
            float4 v = *reinterpret_cast<const float4*>(stage + (size_t)row * 68 + c4);
            float4 bv = *reinterpret_cast<const float4*>(biasTile + c4);
            v.x += bv.x; v.y += bv.y; v.z += bv.z; v.w += bv.w;
            *reinterpret_cast<float4*>(Ctile + (size_t)row * ldc + c4) = v;
        }
    } else {
#pragma unroll
        for (int i = 0; i < 2; i++)
#pragma unroll
            for (int j = 0; j < 2; j++)
                wmma::store_matrix_sync(Ctile + (size_t)(wm * 32 + i * 16) * ldc + wn * 32 + j * 16,
                                        c[i][j], ldc, wmma::mem_row_major);
    }
}

// GEMM1: g_H = inputs(1024x512) @ W^T + bias. grid (8, 16) = 128 blocks.
__global__ __launch_bounds__(128, 2)
void gemm1_tc(const float* __restrict__ A, const float* __restrict__ W,
              const float* __restrict__ bias) {
    const int n0 = blockIdx.x * 64;
    const int m0 = blockIdx.y * 64;
    wmma_core<16, true>(A + (size_t)m0 * FIN, W + (size_t)n0 * FIN,
                        bias + n0, g_H + (size_t)m0 * FOUT + n0, FOUT, FIN);
}

// GEMM2: per-batch Gram partials, split-K2. grid (4, 4, 8 = b*2+kz) = 128 blocks.
__global__ __launch_bounds__(128, 2)
void gemm2_tc() {
    const int b  = blockIdx.z >> 1;
    const int kz = blockIdx.z & 1;
    const int n0 = blockIdx.x * 64;
    const int m0 = blockIdx.y * 64;
    const float* Hb = g_H + (size_t)b * PP * FOUT + kz * 256;
    float* C = (kz ? g_S1 : g_S0) + (size_t)b * PP * PP + (size_t)m0 * PP + n0;
    wmma_core<8, false>(Hb + (size_t)m0 * FOUT, Hb + (size_t)n0 * FOUT, nullptr, C, PP, FOUT);
}

// ================= label-row hashing ========================================
__device__ __forceinline__ unsigned long long mix64(unsigned long long x) {
    x ^= x >> 30; x *= 0xbf58476d1ce4e5b9ULL;
    x ^= x >> 27; x *= 0x94d049bb133111ebULL;
    x ^= x >> 31;
    return x;
}
// 128 blocks x 256 threads = 1024 warps = one warp per label row.
__global__ void hash_kernel(const float* __restrict__ labels) {
    int gt = blockIdx.x * blockDim.x + threadIdx.x;
    if (gt == 0) g_loss = 0.0;
    int warp = gt >> 5;
    int lane = threadIdx.x & 31;
    const float4* row = reinterpret_cast<const float4*>(labels + (size_t)warp * FIN);
    unsigned long long h1 = 0ull, h2 = 0ull;
#pragma unroll
    for (int i = 0; i < 4; i++) {
        float4 v = row[lane + 32 * i];
        int fb = (lane + 32 * i) * 4;
        float vv[4] = {v.x, v.y, v.z, v.w};
#pragma unroll
        for (int j = 0; j < 4; j++) {
            unsigned int bits = __float_as_uint(vv[j]);
            if (vv[j] == 0.0f) bits = 0u;     // canonicalize -0 == +0
            unsigned long long x = (unsigned long long)bits
                ^ ((unsigned long long)(fb + j + 1) * 0x9E3779B97F4A7C15ULL);
            h1 += mix64(x);
            h2 += mix64(x ^ 0xA5A5A5A5DEADBEEFULL);
        }
    }
#pragma unroll
    for (int o = 16; o > 0; o >>= 1) {
        h1 += __shfl_down_sync(0xffffffffu, h1, o);
        h2 += __shfl_down_sync(0xffffffffu, h2, o);
    }
    if (lane == 0) { g_h1[warp] = h1; g_h2[warp] = h2; }
}

// ================= softmax + KL =============================================
// grid (B=4, 32) x 256 threads: 8 warps, one row per warp.
__global__ void softmax_kl_kernel() {
    const int b = blockIdx.x;
    const int rowBase = blockIdx.y * 8;
    __shared__ float inv[PP];
    __shared__ unsigned long long sh1[PP];
    __shared__ unsigned long long sh2[PP];
    __shared__ double wsum[8];

    const int tid = threadIdx.x;
    {
        int t = tid;
        size_t di = ((size_t)b * PP + t) * PP + t;
        float d = g_S0[di] + g_S1[di];           // ||h_t||^2 from Gram diagonal
        inv[t] = 1.0f / fmaxf(sqrtf(d), 1e-12f);
        sh1[t] = g_h1[b * PP + t];
        sh2[t] = g_h2[b * PP + t];
    }
    __syncthreads();

    const int w = tid >> 5, lane = tid & 31;
    const float INV_TAU = 1.0f / 0.07f;
    const int p = rowBase + w;
    const float* S0r = g_S0 + ((size_t)b * PP + p) * PP;
    const float* S1r = g_S1 + ((size_t)b * PP + p) * PP;
    float ip = inv[p] * INV_TAU;
    float s[8];
    float mx = -1e30f;
#pragma unroll
    for (int j = 0; j < 8; j++) {
        int q = lane + 32 * j;
        s[j] = (S0r[q] + S1r[q]) * ip * inv[q];
        mx = fmaxf(mx, s[j]);
    }
#pragma unroll
    for (int o = 16; o > 0; o >>= 1) mx = fmaxf(mx, __shfl_xor_sync(0xffffffffu, mx, o));
    float z = 0.0f;
#pragma unroll
    for (int j = 0; j < 8; j++) z += __expf(s[j] - mx);
#pragma unroll
    for (int o = 16; o > 0; o >>= 1) z += __shfl_xor_sync(0xffffffffu, z, o);
    float lse = mx + logf(z);

    unsigned long long h1p = sh1[p], h2p = sh2[p];
    int cnt = 0;
    bool match[8];
#pragma unroll
    for (int j = 0; j < 8; j++) {
        int q = lane + 32 * j;
        match[j] = (sh1[q] == h1p) && (sh2[q] == h2p);
        cnt += match[j] ? 1 : 0;
    }
#pragma unroll
    for (int o = 16; o > 0; o >>= 1) cnt += __shfl_xor_sync(0xffffffffu, cnt, o);

    float logn = logf((float)cnt);
    float contrib = 0.0f;
#pragma unroll
    for (int j = 0; j < 8; j++) {
        if (match[j]) {
            float lp = s[j] - lse;
            lp = fminf(fmaxf(lp, -11.512925464970229f),      // log(1e-5)
                       -1.0000050000290891e-05f);            // log(1-1e-5)
            contrib += (-logn - lp);
        }
    }
#pragma unroll
    for (int o = 16; o > 0; o >>= 1) contrib += __shfl_xor_sync(0xffffffffu, contrib, o);
    if (lane == 0) wsum[w] = (double)contrib / (double)cnt;
    __syncthreads();
    if (tid == 0) {
        double blk = 0.0;
#pragma unroll
        for (int i = 0; i < 8; i++) blk += wsum[i];
        atomicAdd(&g_loss, blk);
    }
}

__global__ void finalize_kernel(float* __restrict__ out) {
    if (threadIdx.x == 0) out[0] = (float)(g_loss * (1.0 / (double)(BB * PP)));
}

// ================= launch ====================================================
extern "C" void kernel_launch(void* const* d_in, const int* in_sizes, int n_in,
                              void* d_out, int out_size) {
    const float* inputs = (const float*)d_in[0];
    const float* labels = (const float*)d_in[1];
    const float* W      = (const float*)d_in[2];
    const float* bias   = (const float*)d_in[3];
    float* out = (float*)d_out;

    hash_kernel<<<128, 256>>>(labels);
    gemm1_tc<<<dim3(FOUT / 64, NROWS / 64), 128>>>(inputs, W, bias);
    gemm2_tc<<<dim3(PP / 64, PP / 64, BB * 2), 128>>>();
    softmax_kl_kernel<<<dim3(BB, PP / 8), 256>>>();
    finalize_kernel<<<1, 32>>>(out);
}